// round 2
// baseline (speedup 1.0000x reference)
#include <cuda_runtime.h>
#include <cuda_bf16.h>
#include <cstdint>

// Problem constants
#define BATCH 256
#define EDIM  512
#define NNODES 16383
#define NPAD  16384
#define DEPTH 14
#define KSPLIT 1024   // [high(512) | low(512)] halves of split-bf16 operands

// Scratch (static device globals: allocation-free rule)
__device__ __nv_bfloat16 g_A[BATCH * KSPLIT];      // [xh | xl]  (256 x 1024)
__device__ __nv_bfloat16 g_B[NPAD * KSPLIT];       // [wh | wl]  (16384 x 1024), row 16383 stays zero
__device__ float         g_db[NPAD];               // b[:,1]-b[:,0], idx 16383 stays zero
__device__ float         g_S[BATCH * NPAD];        // delta logits

// ---------------------------------------------------------------------------
// Prep A: split x into bf16 high/low parts
// ---------------------------------------------------------------------------
__global__ void prepA_kernel(const float* __restrict__ x) {
    int idx = blockIdx.x * blockDim.x + threadIdx.x;   // 0 .. 131071
    int b = idx >> 9;
    int e = idx & 511;
    float v = x[idx];
    __nv_bfloat16 hi = __float2bfloat16_rn(v);
    __nv_bfloat16 lo = __float2bfloat16_rn(v - __bfloat162float(hi));
    g_A[b * KSPLIT + e]       = hi;
    g_A[b * KSPLIT + 512 + e] = lo;
}

// ---------------------------------------------------------------------------
// Prep B: dW = W[:,:,1]-W[:,:,0], split into bf16 high/low; also db
// ---------------------------------------------------------------------------
__global__ void prepB_kernel(const float* __restrict__ W, const float* __restrict__ bvec) {
    int idx = blockIdx.x * blockDim.x + threadIdx.x;
    if (idx >= NNODES * 128) return;
    int n  = idx >> 7;          // node
    int eq = idx & 127;         // quad of e
    int e  = eq << 2;           // e, e+1, e+2, e+3

    const float4* wp = reinterpret_cast<const float4*>(W + (size_t)n * 1024 + e * 2);
    float4 f0 = wp[0];   // (W[n,e,0], W[n,e,1], W[n,e+1,0], W[n,e+1,1])
    float4 f1 = wp[1];

    float d0 = f0.y - f0.x;
    float d1 = f0.w - f0.z;
    float d2 = f1.y - f1.x;
    float d3 = f1.w - f1.z;

    __nv_bfloat16 h0 = __float2bfloat16_rn(d0), h1 = __float2bfloat16_rn(d1);
    __nv_bfloat16 h2 = __float2bfloat16_rn(d2), h3 = __float2bfloat16_rn(d3);
    __nv_bfloat16 l0 = __float2bfloat16_rn(d0 - __bfloat162float(h0));
    __nv_bfloat16 l1 = __float2bfloat16_rn(d1 - __bfloat162float(h1));
    __nv_bfloat16 l2 = __float2bfloat16_rn(d2 - __bfloat162float(h2));
    __nv_bfloat16 l3 = __float2bfloat16_rn(d3 - __bfloat162float(h3));

    __nv_bfloat162* hdst = reinterpret_cast<__nv_bfloat162*>(&g_B[(size_t)n * KSPLIT + e]);
    hdst[0] = __halves2bfloat162(h0, h1);
    hdst[1] = __halves2bfloat162(h2, h3);
    __nv_bfloat162* ldst = reinterpret_cast<__nv_bfloat162*>(&g_B[(size_t)n * KSPLIT + 512 + e]);
    ldst[0] = __halves2bfloat162(l0, l1);
    ldst[1] = __halves2bfloat162(l2, l3);

    if (eq == 0) {
        g_db[n] = bvec[2 * n + 1] - bvec[2 * n];
    }
}

// ---------------------------------------------------------------------------
// GEMM: S[m][n] = sum over effective K=1536 of split-bf16 products + db[n]
//   phase 0: xh . wh   phase 1: xl . wh   phase 2: xh . wl
// Block tile 256(M) x 128(N), K-tile 32. 8 warps, warp tile 64x64.
// ---------------------------------------------------------------------------
__device__ __forceinline__ void mma16816(float* acc, const uint32_t* a, const uint32_t* b) {
    asm volatile(
        "mma.sync.aligned.m16n8k16.row.col.f32.bf16.bf16.f32 "
        "{%0,%1,%2,%3}, {%4,%5,%6,%7}, {%8,%9}, {%0,%1,%2,%3};\n"
        : "+f"(acc[0]), "+f"(acc[1]), "+f"(acc[2]), "+f"(acc[3])
        : "r"(a[0]), "r"(a[1]), "r"(a[2]), "r"(a[3]), "r"(b[0]), "r"(b[1]));
}

__global__ void __launch_bounds__(256) gemm_kernel() {
    __shared__ __nv_bfloat16 As[256][40];   // 256 x 32, pad to 40 (conflict-free frag loads)
    __shared__ __nv_bfloat16 Bs[128][40];

    const int tid  = threadIdx.x;
    const int lane = tid & 31;
    const int warp = tid >> 5;
    const int wm   = warp >> 1;   // 0..3  -> M base wm*64
    const int wn   = warp & 1;    // 0..1  -> N base wn*64
    const int ntile = blockIdx.x * 128;

    float acc[4][8][4];
#pragma unroll
    for (int mi = 0; mi < 4; ++mi)
#pragma unroll
        for (int ni = 0; ni < 8; ++ni)
#pragma unroll
            for (int q = 0; q < 4; ++q) acc[mi][ni][q] = 0.f;

    const __nv_bfloat16* gA = g_A;
    const __nv_bfloat16* gB = g_B + (size_t)ntile * KSPLIT;

    for (int kk = 0; kk < 48; ++kk) {
        int phase = kk >> 4;
        int ko    = (kk & 15) << 5;
        int a_off = (phase == 1) ? (512 + ko) : ko;
        int b_off = (phase == 2) ? (512 + ko) : ko;

        // Load A tile: 256x32 bf16 = 1024 uint4, 4 per thread
#pragma unroll
        for (int j = 0; j < 4; ++j) {
            int u = tid + 256 * j;
            int row = u >> 2, chunk = u & 3;
            uint4 v = *reinterpret_cast<const uint4*>(gA + row * KSPLIT + a_off + chunk * 8);
            *reinterpret_cast<uint4*>(&As[row][chunk * 8]) = v;
        }
        // Load B tile: 128x32 bf16 = 512 uint4, 2 per thread
#pragma unroll
        for (int j = 0; j < 2; ++j) {
            int u = tid + 256 * j;
            int row = u >> 2, chunk = u & 3;
            uint4 v = *reinterpret_cast<const uint4*>(gB + (size_t)row * KSPLIT + b_off + chunk * 8);
            *reinterpret_cast<uint4*>(&Bs[row][chunk * 8]) = v;
        }
        __syncthreads();

#pragma unroll
        for (int ks = 0; ks < 32; ks += 16) {
            const int kc = ks + ((lane & 3) << 1);
            uint32_t a[4][4];
#pragma unroll
            for (int mi = 0; mi < 4; ++mi) {
                int r0 = wm * 64 + mi * 16 + (lane >> 2);
                a[mi][0] = *reinterpret_cast<const uint32_t*>(&As[r0][kc]);
                a[mi][1] = *reinterpret_cast<const uint32_t*>(&As[r0 + 8][kc]);
                a[mi][2] = *reinterpret_cast<const uint32_t*>(&As[r0][kc + 8]);
                a[mi][3] = *reinterpret_cast<const uint32_t*>(&As[r0 + 8][kc + 8]);
            }
            uint32_t bf[8][2];
#pragma unroll
            for (int ni = 0; ni < 8; ++ni) {
                int nb = wn * 64 + ni * 8 + (lane >> 2);
                bf[ni][0] = *reinterpret_cast<const uint32_t*>(&Bs[nb][kc]);
                bf[ni][1] = *reinterpret_cast<const uint32_t*>(&Bs[nb][kc + 8]);
            }
#pragma unroll
            for (int mi = 0; mi < 4; ++mi)
#pragma unroll
                for (int ni = 0; ni < 8; ++ni)
                    mma16816(acc[mi][ni], a[mi], bf[ni]);
        }
        __syncthreads();
    }

    // Epilogue: add db, store fp32 delta
#pragma unroll
    for (int ni = 0; ni < 8; ++ni) {
        int col = ntile + wn * 64 + ni * 8 + ((lane & 3) << 1);
        float db0 = g_db[col];
        float db1 = g_db[col + 1];
#pragma unroll
        for (int mi = 0; mi < 4; ++mi) {
            int row = wm * 64 + mi * 16 + (lane >> 2);
            float2 v0 = make_float2(acc[mi][ni][0] + db0, acc[mi][ni][1] + db1);
            float2 v1 = make_float2(acc[mi][ni][2] + db0, acc[mi][ni][3] + db1);
            *reinterpret_cast<float2*>(&g_S[(size_t)row * NPAD + col]) = v0;
            *reinterpret_cast<float2*>(&g_S[(size_t)(row + 8) * NPAD + col]) = v1;
        }
    }
}

// ---------------------------------------------------------------------------
// Tree kernel: level-by-level prefix products of sigmoid probabilities.
// One block per batch row. out[b][v] = prod over ancestors.
// ---------------------------------------------------------------------------
__device__ __forceinline__ void sig2(float delta, float& p0, float& p1) {
    float dc = fminf(fmaxf(delta, -30.f), 30.f);
    float t = __expf(-dc);                 // e^{-delta}
    float r = __fdividef(1.f, 1.f + t);    // p(bit=1)
    p1 = r;
    p0 = t * r;                            // p(bit=0)
}

__global__ void __launch_bounds__(512) tree_kernel(float* __restrict__ out) {
    __shared__ float X[8192];   // outputs of even depths
    __shared__ float Y[4096];   // outputs of odd depths
    const int b = blockIdx.x;
    const int tid = threadIdx.x;
    const float* Srow = g_S + (size_t)b * NPAD;

    if (tid == 0) {   // depth 0: root node 0
        float p0, p1;
        sig2(Srow[0], p0, p1);
        X[0] = p0;
        X[1] = p1;
    }
    __syncthreads();

#pragma unroll
    for (int d = 1; d <= 12; ++d) {
        const int L = 1 << d;
        float* cur = (d & 1) ? X : Y;   // output of depth d-1
        float* nxt = (d & 1) ? Y : X;
        for (int i = tid; i < L; i += 512) {
            float p0, p1;
            sig2(Srow[(L - 1) + i], p0, p1);
            float c = cur[i];
            nxt[2 * i]     = c * p0;
            nxt[2 * i + 1] = c * p1;
        }
        __syncthreads();
    }

    // depth 13: read X (8192 prefixes), write leaves directly to gmem
    float2* orow = reinterpret_cast<float2*>(out + (size_t)b * NPAD);
    for (int i = tid; i < 8192; i += 512) {
        float p0, p1;
        sig2(Srow[8191 + i], p0, p1);
        float c = X[i];
        orow[i] = make_float2(c * p0, c * p1);
    }
}

// ---------------------------------------------------------------------------
// Launch
// ---------------------------------------------------------------------------
extern "C" void kernel_launch(void* const* d_in, const int* in_sizes, int n_in,
                              void* d_out, int out_size) {
    const float* x = (const float*)d_in[0];
    const float* W = (const float*)d_in[1];
    const float* b = (const float*)d_in[2];
    // d_in[3] (path_nodes) and d_in[4] (path_bits) encode a perfect heap; recomputed implicitly.
    float* out = (float*)d_out;

    prepA_kernel<<<512, 256>>>(x);
    prepB_kernel<<<(NNODES * 128 + 255) / 256, 256>>>(W, b);
    gemm_kernel<<<NPAD / 128, 256>>>();
    tree_kernel<<<BATCH, 512>>>(out);
}

// round 5
// speedup vs baseline: 1.5742x; 1.5742x over previous
#include <cuda_runtime.h>
#include <cuda_bf16.h>
#include <cstdint>

#define BATCH  256
#define EDIM   512
#define NNODES 16383
#define NPAD   16384

// ---------------------------------------------------------------------------
// Scratch (static device globals: allocation-free rule)
// ---------------------------------------------------------------------------
__device__ __nv_bfloat16 g_A[BATCH * 1024];   // [xh(512) | xl(512)] per batch row
__device__ float         g_S[BATCH * NPAD];   // delta logits

// ---------------------------------------------------------------------------
// Prep A: split x into bf16 high/low parts
// ---------------------------------------------------------------------------
__global__ void prepA_kernel(const float* __restrict__ x) {
    int idx = blockIdx.x * blockDim.x + threadIdx.x;   // 0 .. 131071
    int b = idx >> 9;
    int e = idx & 511;
    float v = x[idx];
    __nv_bfloat16 hi = __float2bfloat16_rn(v);
    __nv_bfloat16 lo = __float2bfloat16_rn(v - __bfloat162float(hi));
    g_A[b * 1024 + e]       = hi;
    g_A[b * 1024 + 512 + e] = lo;
}

// ---------------------------------------------------------------------------
// cp.async helpers (sm_80 baseline ISA -- compiles for plain sm_100)
// ---------------------------------------------------------------------------
__device__ __forceinline__ uint32_t smem_u32(const void* p) {
    uint32_t a;
    asm("{ .reg .u64 t; cvta.to.shared.u64 t, %1; cvt.u32.u64 %0, t; }" : "=r"(a) : "l"(p));
    return a;
}
__device__ __forceinline__ void cp16(uint32_t dst, const void* src) {
    asm volatile("cp.async.ca.shared.global [%0], [%1], 16;" :: "r"(dst), "l"(src));
}
__device__ __forceinline__ void cp16z(uint32_t dst, const void* src, uint32_t src_bytes) {
    asm volatile("cp.async.ca.shared.global [%0], [%1], 16, %2;"
                 :: "r"(dst), "l"(src), "r"(src_bytes));
}
#define CP_COMMIT() asm volatile("cp.async.commit_group;" ::: "memory")
#define CP_WAIT0()  asm volatile("cp.async.wait_group 0;" ::: "memory")

// ---------------------------------------------------------------------------
// mma.sync m16n8k16 bf16 (known-correct fragment mapping from R2)
// ---------------------------------------------------------------------------
__device__ __forceinline__ void mma16816(float* acc, const uint32_t* a, const uint32_t* b) {
    asm volatile(
        "mma.sync.aligned.m16n8k16.row.col.f32.bf16.bf16.f32 "
        "{%0,%1,%2,%3}, {%4,%5,%6,%7}, {%8,%9}, {%0,%1,%2,%3};\n"
        : "+f"(acc[0]), "+f"(acc[1]), "+f"(acc[2]), "+f"(acc[3])
        : "r"(a[0]), "r"(a[1]), "r"(a[2]), "r"(a[3]), "r"(b[0]), "r"(b[1]));
}

// ---------------------------------------------------------------------------
// Fused GEMM: S[m][n] = dx . dW_split + db
//   Block: M=256 (all batch) x N=128 nodes. K = 512 fp32 in 16 chunks of 32.
//   Per chunk: cp.async A hi/lo bf16 tiles + raw W float4 slice into SMEM,
//   convert W -> Bh/Bl bf16 tiles, then 3-phase mma (Ah.Bh, Al.Bh, Ah.Bl).
//   2-stage ring, loads for chunk c+1 overlap MMAs of chunk c.
//   SMEM tiles: pitch 40 bf16 (80 B) -> conflict-free 32-bit frag loads.
//   Raw W per chunk: 128 nodes x 64 floats (2 raw per e) = 32768 B.
// ---------------------------------------------------------------------------
#define STAGE     94208
#define OFF_AH    0          // 256 x 40bf16 = 20480 B
#define OFF_AL    20480
#define OFF_BH    40960      // 128 x 40bf16 = 10240 B
#define OFF_BL    51200
#define OFF_WR    61440      // raw W floats: 128 nodes x 64 floats x 4 B = 32768 B
#define OFF_DB    (2 * STAGE)            // 188416
#define GEMM_SMEM (OFF_DB + 512)         // 188928 B

__global__ void __launch_bounds__(256) gemm_f(const float* __restrict__ W,
                                              const float* __restrict__ bvec) {
    extern __shared__ char smem[];
    const uint32_t sb = smem_u32(smem);
    const int tid  = threadIdx.x;
    const int lane = tid & 31;
    const int warp = tid >> 5;
    const int wm   = warp >> 1;   // 0..3 -> M base wm*64
    const int wn   = warp & 1;    // 0..1 -> N base wn*64
    const int ntile = blockIdx.x * 128;

    float* db_s = reinterpret_cast<float*>(smem + OFF_DB);
    if (tid < 128) {
        int col = ntile + tid;
        db_s[tid] = (col < NNODES) ? (bvec[2 * col + 1] - bvec[2 * col]) : 0.f;
    }

    float acc[4][8][4];
#pragma unroll
    for (int mi = 0; mi < 4; ++mi)
#pragma unroll
        for (int ni = 0; ni < 8; ++ni)
#pragma unroll
            for (int q = 0; q < 4; ++q) acc[mi][ni][q] = 0.f;

    // ---- issue async loads for chunk c into stage c&1 ----
    auto issue = [&](int c) {
        const uint32_t stg = sb + (uint32_t)(c & 1) * STAGE;
        // A tiles: 256 rows x 32 bf16 (64 B = 4 x 16 B) x {hi,lo} = 2048 chunks
#pragma unroll
        for (int j = 0; j < 8; ++j) {
            int u = tid + 256 * j;
            int h = u >> 10;          // 0=hi, 1=lo
            int v = u & 1023;
            int row = v >> 2;
            int c16 = v & 3;
            const char* src = reinterpret_cast<const char*>(
                g_A + (size_t)row * 1024 + h * 512 + c * 32) + c16 * 16;
            cp16(stg + (h ? OFF_AL : OFF_AH) + row * 80 + c16 * 16, src);
        }
        // raw W: 128 nodes x 64 consecutive floats (256 B = 16 x 16 B) = 2048 chunks
#pragma unroll
        for (int j = 0; j < 8; ++j) {
            int p  = tid + 256 * j;
            int nl = p >> 4;
            int e2 = p & 15;
            int ng = ntile + nl;
            int ok = (ng < NNODES);
            const char* src = reinterpret_cast<const char*>(
                W + (size_t)(ok ? ng : 0) * 1024 + c * 64) + e2 * 16;
            cp16z(stg + OFF_WR + p * 16, src, ok ? 16u : 0u);
        }
        CP_COMMIT();
    };

    // ---- convert raw W floats -> Bh/Bl bf16 tiles (same-thread chunks) ----
    auto convert = [&](int c) {
        char* base = smem + (size_t)(c & 1) * STAGE;
#pragma unroll
        for (int j = 0; j < 8; ++j) {
            int p  = tid + 256 * j;
            int nl = p >> 4;
            int e2 = p & 15;
            float4 w = *reinterpret_cast<const float4*>(base + OFF_WR + p * 16);
            float d0 = w.y - w.x;
            float d1 = w.w - w.z;
            __nv_bfloat16 h0 = __float2bfloat16_rn(d0), h1 = __float2bfloat16_rn(d1);
            __nv_bfloat16 l0 = __float2bfloat16_rn(d0 - __bfloat162float(h0));
            __nv_bfloat16 l1 = __float2bfloat16_rn(d1 - __bfloat162float(h1));
            *reinterpret_cast<__nv_bfloat162*>(base + OFF_BH + nl * 80 + e2 * 4) =
                __halves2bfloat162(h0, h1);
            *reinterpret_cast<__nv_bfloat162*>(base + OFF_BL + nl * 80 + e2 * 4) =
                __halves2bfloat162(l0, l1);
        }
    };

    // prologue: stage 0
    issue(0);
    CP_WAIT0();          // own-thread cp.async data visible to self
    convert(0);          // reads exactly the chunks this thread issued
    __syncthreads();

    for (int c = 0; c < 16; ++c) {
        if (c < 15) issue(c + 1);

        // ---- MMAs on stage c&1 ----
        const char* base = smem + (size_t)(c & 1) * STAGE;
#pragma unroll
        for (int ks = 0; ks < 32; ks += 16) {
            const int kc = ks + ((lane & 3) << 1);
            uint32_t a_h[4][4], a_l[4][4], b_h[8][2], b_l[8][2];
#pragma unroll
            for (int mi = 0; mi < 4; ++mi) {
                int r0 = wm * 64 + mi * 16 + (lane >> 2);
                const char* pa = base + r0 * 80 + kc * 2;
                a_h[mi][0] = *reinterpret_cast<const uint32_t*>(pa + OFF_AH);
                a_h[mi][1] = *reinterpret_cast<const uint32_t*>(pa + OFF_AH + 8 * 80);
                a_h[mi][2] = *reinterpret_cast<const uint32_t*>(pa + OFF_AH + 16);
                a_h[mi][3] = *reinterpret_cast<const uint32_t*>(pa + OFF_AH + 8 * 80 + 16);
                a_l[mi][0] = *reinterpret_cast<const uint32_t*>(pa + OFF_AL);
                a_l[mi][1] = *reinterpret_cast<const uint32_t*>(pa + OFF_AL + 8 * 80);
                a_l[mi][2] = *reinterpret_cast<const uint32_t*>(pa + OFF_AL + 16);
                a_l[mi][3] = *reinterpret_cast<const uint32_t*>(pa + OFF_AL + 8 * 80 + 16);
            }
#pragma unroll
            for (int ni = 0; ni < 8; ++ni) {
                int nb = wn * 64 + ni * 8 + (lane >> 2);
                const char* pb = base + nb * 80 + kc * 2;
                b_h[ni][0] = *reinterpret_cast<const uint32_t*>(pb + OFF_BH);
                b_h[ni][1] = *reinterpret_cast<const uint32_t*>(pb + OFF_BH + 16);
                b_l[ni][0] = *reinterpret_cast<const uint32_t*>(pb + OFF_BL);
                b_l[ni][1] = *reinterpret_cast<const uint32_t*>(pb + OFF_BL + 16);
            }
#pragma unroll
            for (int mi = 0; mi < 4; ++mi)
#pragma unroll
                for (int ni = 0; ni < 8; ++ni)
                    mma16816(acc[mi][ni], a_h[mi], b_h[ni]);
#pragma unroll
            for (int mi = 0; mi < 4; ++mi)
#pragma unroll
                for (int ni = 0; ni < 8; ++ni)
                    mma16816(acc[mi][ni], a_l[mi], b_h[ni]);
#pragma unroll
            for (int mi = 0; mi < 4; ++mi)
#pragma unroll
                for (int ni = 0; ni < 8; ++ni)
                    mma16816(acc[mi][ni], a_h[mi], b_l[ni]);
        }

        if (c < 15) {
            CP_WAIT0();        // chunk c+1 data landed (overlapped with MMAs above)
            convert(c + 1);
        }
        __syncthreads();
    }

    // ---- epilogue: add db, store fp32 delta ----
#pragma unroll
    for (int ni = 0; ni < 8; ++ni) {
        int colL = wn * 64 + ni * 8 + ((lane & 3) << 1);
        int col  = ntile + colL;
        float db0 = db_s[colL];
        float db1 = db_s[colL + 1];
#pragma unroll
        for (int mi = 0; mi < 4; ++mi) {
            int row = wm * 64 + mi * 16 + (lane >> 2);
            float2 v0 = make_float2(acc[mi][ni][0] + db0, acc[mi][ni][1] + db1);
            float2 v1 = make_float2(acc[mi][ni][2] + db0, acc[mi][ni][3] + db1);
            *reinterpret_cast<float2*>(&g_S[(size_t)row * NPAD + col]) = v0;
            *reinterpret_cast<float2*>(&g_S[(size_t)(row + 8) * NPAD + col]) = v1;
        }
    }
}

// ---------------------------------------------------------------------------
// Tree kernel v2: 8 subtrees per batch row (depth-3 roots), grid (8, 256).
// Top-3-level prefix computed redundantly per block; then level sweep in smem.
// ---------------------------------------------------------------------------
__device__ __forceinline__ void sig2(float delta, float& p0, float& p1) {
    float dc = fminf(fmaxf(delta, -30.f), 30.f);
    float t = __expf(-dc);
    float r = __fdividef(1.f, 1.f + t);
    p1 = r;
    p0 = t * r;
}

__global__ void __launch_bounds__(256) tree_kernel(float* __restrict__ out) {
    __shared__ float bufA[1024];
    __shared__ float bufB[1024];
    const int r   = blockIdx.x;   // subtree (depth-3 node index) 0..7
    const int b   = blockIdx.y;   // batch row
    const int tid = threadIdx.x;
    const float* S = g_S + (size_t)b * NPAD;

    // prefix through depths 0..2 along the path to depth-3 node r
    float P;
    {
        float p0, p1;
        sig2(S[0], p0, p1);                 P  = (r & 4) ? p1 : p0;
        sig2(S[1 + (r >> 2)], p0, p1);      P *= (r & 2) ? p1 : p0;
        sig2(S[3 + (r >> 1)], p0, p1);      P *= (r & 1) ? p1 : p0;
    }
    if (tid == 0) bufA[0] = P;
    __syncthreads();

    float* cur = bufA;
    float* nxt = bufB;
    int L = 1;
#pragma unroll
    for (int d = 3; d <= 12; ++d) {
        const int base = (1 << d) - 1 + r * L;
        for (int i = tid; i < L; i += 256) {
            float p0, p1;
            sig2(S[base + i], p0, p1);
            float cc = cur[i];
            nxt[2 * i]     = cc * p0;
            nxt[2 * i + 1] = cc * p1;
        }
        __syncthreads();
        float* t = cur; cur = nxt; nxt = t;
        L <<= 1;
    }

    // depth 13: L = 1024, write leaves straight to gmem
    float2* orow = reinterpret_cast<float2*>(out + (size_t)b * NPAD) + r * 1024;
    const int base = 8191 + r * 1024;
    for (int i = tid; i < 1024; i += 256) {
        float p0, p1;
        sig2(S[base + i], p0, p1);
        float cc = cur[i];
        orow[i] = make_float2(cc * p0, cc * p1);
    }
}

// ---------------------------------------------------------------------------
// Launch
// ---------------------------------------------------------------------------
extern "C" void kernel_launch(void* const* d_in, const int* in_sizes, int n_in,
                              void* d_out, int out_size) {
    const float* x    = (const float*)d_in[0];
    const float* W    = (const float*)d_in[1];
    const float* bvec = (const float*)d_in[2];
    // d_in[3]/d_in[4] (path_nodes/path_bits) encode a perfect heap; implicit.
    float* out = (float*)d_out;

    cudaFuncSetAttribute(gemm_f, cudaFuncAttributeMaxDynamicSharedMemorySize, GEMM_SMEM);

    prepA_kernel<<<512, 256>>>(x);
    gemm_f<<<128, 256, GEMM_SMEM>>>(W, bvec);
    tree_kernel<<<dim3(8, BATCH), 256>>>(out);
}

// round 7
// speedup vs baseline: 1.6707x; 1.0613x over previous
#include <cuda_runtime.h>
#include <cuda_bf16.h>
#include <cstdint>

#define BATCH  256
#define EDIM   512
#define NNODES 16383
#define NPAD   16384

// ---------------------------------------------------------------------------
// Scratch (static device globals: allocation-free rule)
// ---------------------------------------------------------------------------
__device__ __nv_bfloat16 g_A[BATCH * 1024];   // [xh(512) | xl(512)] per batch row
__device__ float         g_S[BATCH * NPAD];   // delta logits

// ---------------------------------------------------------------------------
// Prep A: split x into bf16 high/low parts (vectorized: float4 per thread)
// ---------------------------------------------------------------------------
__global__ void prepA_kernel(const float* __restrict__ x) {
    int idx = blockIdx.x * blockDim.x + threadIdx.x;   // 0 .. 32767 float4s
    int b  = idx >> 7;            // 128 float4 per batch row
    int e4 = (idx & 127) * 4;
    float4 v = reinterpret_cast<const float4*>(x)[idx];
    __nv_bfloat16 h0 = __float2bfloat16_rn(v.x), h1 = __float2bfloat16_rn(v.y);
    __nv_bfloat16 h2 = __float2bfloat16_rn(v.z), h3 = __float2bfloat16_rn(v.w);
    __nv_bfloat16 l0 = __float2bfloat16_rn(v.x - __bfloat162float(h0));
    __nv_bfloat16 l1 = __float2bfloat16_rn(v.y - __bfloat162float(h1));
    __nv_bfloat16 l2 = __float2bfloat16_rn(v.z - __bfloat162float(h2));
    __nv_bfloat16 l3 = __float2bfloat16_rn(v.w - __bfloat162float(h3));
    __nv_bfloat162* hd = reinterpret_cast<__nv_bfloat162*>(g_A + b * 1024 + e4);
    hd[0] = __halves2bfloat162(h0, h1);
    hd[1] = __halves2bfloat162(h2, h3);
    __nv_bfloat162* ld = reinterpret_cast<__nv_bfloat162*>(g_A + b * 1024 + 512 + e4);
    ld[0] = __halves2bfloat162(l0, l1);
    ld[1] = __halves2bfloat162(l2, l3);
}

// ---------------------------------------------------------------------------
// cp.async + ldmatrix helpers (sm_80/75 baseline ISA -- compiles for sm_100)
// ---------------------------------------------------------------------------
__device__ __forceinline__ uint32_t smem_u32(const void* p) {
    uint32_t a;
    asm("{ .reg .u64 t; cvta.to.shared.u64 t, %1; cvt.u32.u64 %0, t; }" : "=r"(a) : "l"(p));
    return a;
}
__device__ __forceinline__ void cp16(uint32_t dst, const void* src) {
    asm volatile("cp.async.ca.shared.global [%0], [%1], 16;" :: "r"(dst), "l"(src));
}
__device__ __forceinline__ void cp16z(uint32_t dst, const void* src, uint32_t src_bytes) {
    asm volatile("cp.async.ca.shared.global [%0], [%1], 16, %2;"
                 :: "r"(dst), "l"(src), "r"(src_bytes));
}
#define CP_COMMIT() asm volatile("cp.async.commit_group;" ::: "memory")
#define CP_WAIT0()  asm volatile("cp.async.wait_group 0;" ::: "memory")

__device__ __forceinline__ void ldsm4(uint32_t* r, uint32_t addr) {
    asm volatile("ldmatrix.sync.aligned.m8n8.x4.shared.b16 {%0,%1,%2,%3}, [%4];"
                 : "=r"(r[0]), "=r"(r[1]), "=r"(r[2]), "=r"(r[3]) : "r"(addr));
}

__device__ __forceinline__ void mma16816(float* acc, const uint32_t* a, uint32_t b0, uint32_t b1) {
    asm volatile(
        "mma.sync.aligned.m16n8k16.row.col.f32.bf16.bf16.f32 "
        "{%0,%1,%2,%3}, {%4,%5,%6,%7}, {%8,%9}, {%0,%1,%2,%3};\n"
        : "+f"(acc[0]), "+f"(acc[1]), "+f"(acc[2]), "+f"(acc[3])
        : "r"(a[0]), "r"(a[1]), "r"(a[2]), "r"(a[3]), "r"(b0), "r"(b1));
}

// ---------------------------------------------------------------------------
// Fused GEMM: S[m][n] = dx . dW_split + db
//   512 threads / 16 warps; warp tile 64(M) x 32(N). Block M=256 x N=128.
//   K = 512 fp32 in 16 chunks of 32; 2-stage cp.async ring; W converted
//   in-SMEM to hi/lo bf16; fragments via ldmatrix. 3 mma phases per k-step.
// ---------------------------------------------------------------------------
#define STAGE     94208
#define OFF_AH    0          // 256 x 40bf16 (pitch 80 B) = 20480 B
#define OFF_AL    20480
#define OFF_BH    40960      // 128 x 40bf16 = 10240 B
#define OFF_BL    51200
#define OFF_WR    61440      // raw W floats: 128 nodes x 64 floats x 4 B = 32768 B
#define OFF_DB    (2 * STAGE)            // 188416
#define GEMM_SMEM (OFF_DB + 512)         // 188928 B

__global__ void __launch_bounds__(512) gemm_f(const float* __restrict__ W,
                                              const float* __restrict__ bvec) {
    extern __shared__ char smem[];
    const uint32_t sb = smem_u32(smem);
    const int tid  = threadIdx.x;
    const int lane = tid & 31;
    const int warp = tid >> 5;
    const int wm   = warp >> 2;   // 0..3 -> M base wm*64
    const int wn   = warp & 3;    // 0..3 -> N base wn*32
    const int ntile = blockIdx.x * 128;

    float* db_s = reinterpret_cast<float*>(smem + OFF_DB);
    if (tid < 128) {
        int col = ntile + tid;
        db_s[tid] = (col < NNODES) ? (bvec[2 * col + 1] - bvec[2 * col]) : 0.f;
    }

    float acc[4][4][4];
#pragma unroll
    for (int mi = 0; mi < 4; ++mi)
#pragma unroll
        for (int ni = 0; ni < 4; ++ni)
#pragma unroll
            for (int q = 0; q < 4; ++q) acc[mi][ni][q] = 0.f;

    // ldmatrix per-lane address components (within a stage, before OFF_*)
    //  A (m16k16): lanes 0-7 rows+0 k+0 | 8-15 rows+8 k+0 | 16-23 rows+0 k+8 | 24-31 rows+8 k+8
    const int a_row = wm * 64 + (lane & 7) + ((lane >> 3) & 1) * 8;
    const int a_col = (lane >> 4) * 8;
    //  B (two n8k16 tiles): 0-7 n+0 k+0 | 8-15 n+0 k+8 | 16-23 n+8 k+0 | 24-31 n+8 k+8
    const int b_row = wn * 32 + (lane & 7) + ((lane >> 4) & 1) * 8;
    const int b_col = ((lane >> 3) & 1) * 8;

    // ---- issue async loads for chunk c into stage c&1 ----
    auto issue = [&](int c) {
        const uint32_t stg = sb + (uint32_t)(c & 1) * STAGE;
        // A tiles: 256 rows x 32 bf16 (4 x 16 B) x {hi,lo} = 2048 chunks, 4/thread
#pragma unroll
        for (int j = 0; j < 4; ++j) {
            int u = tid + 512 * j;
            int h = u >> 10;          // 0=hi, 1=lo
            int v = u & 1023;
            int row = v >> 2;
            int c16 = v & 3;
            const char* src = reinterpret_cast<const char*>(
                g_A + (size_t)row * 1024 + h * 512 + c * 32) + c16 * 16;
            cp16(stg + (h ? OFF_AL : OFF_AH) + row * 80 + c16 * 16, src);
        }
        // raw W: 128 nodes x 64 consecutive floats (16 x 16 B) = 2048 chunks, 4/thread
#pragma unroll
        for (int j = 0; j < 4; ++j) {
            int p  = tid + 512 * j;
            int nl = p >> 4;
            int e2 = p & 15;
            int ng = ntile + nl;
            int ok = (ng < NNODES);
            const char* src = reinterpret_cast<const char*>(
                W + (size_t)(ok ? ng : 0) * 1024 + c * 64) + e2 * 16;
            cp16z(stg + OFF_WR + p * 16, src, ok ? 16u : 0u);
        }
        CP_COMMIT();
    };

    // ---- convert raw W floats -> Bh/Bl bf16 tiles (same-thread chunks) ----
    auto convert = [&](int c) {
        char* base = smem + (size_t)(c & 1) * STAGE;
#pragma unroll
        for (int j = 0; j < 4; ++j) {
            int p  = tid + 512 * j;
            int nl = p >> 4;
            int e2 = p & 15;
            float4 w = *reinterpret_cast<const float4*>(base + OFF_WR + p * 16);
            float d0 = w.y - w.x;
            float d1 = w.w - w.z;
            __nv_bfloat16 h0 = __float2bfloat16_rn(d0), h1 = __float2bfloat16_rn(d1);
            __nv_bfloat16 l0 = __float2bfloat16_rn(d0 - __bfloat162float(h0));
            __nv_bfloat16 l1 = __float2bfloat16_rn(d1 - __bfloat162float(h1));
            *reinterpret_cast<__nv_bfloat162*>(base + OFF_BH + nl * 80 + e2 * 4) =
                __halves2bfloat162(h0, h1);
            *reinterpret_cast<__nv_bfloat162*>(base + OFF_BL + nl * 80 + e2 * 4) =
                __halves2bfloat162(l0, l1);
        }
    };

    // prologue: stage 0
    issue(0);
    CP_WAIT0();          // own-thread cp.async data visible to self
    convert(0);          // reads exactly the chunks this thread issued
    __syncthreads();

    for (int c = 0; c < 16; ++c) {
        if (c < 15) issue(c + 1);

        // ---- MMAs on stage c&1 ----
        const uint32_t stg = sb + (uint32_t)(c & 1) * STAGE;
#pragma unroll
        for (int ks = 0; ks < 32; ks += 16) {
            const uint32_t a_addr = stg + (uint32_t)(a_row * 80 + (ks + a_col) * 2);
            const uint32_t b_addr = stg + (uint32_t)(b_row * 80 + (ks + b_col) * 2);

            uint32_t ah[4][4], bh[2][4];
#pragma unroll
            for (int mi = 0; mi < 4; ++mi) ldsm4(ah[mi], a_addr + OFF_AH + mi * 16 * 80);
#pragma unroll
            for (int q = 0; q < 2; ++q)    ldsm4(bh[q], b_addr + OFF_BH + q * 16 * 80);
#pragma unroll
            for (int mi = 0; mi < 4; ++mi)
#pragma unroll
                for (int ni = 0; ni < 4; ++ni)
                    mma16816(acc[mi][ni], ah[mi], bh[ni >> 1][(ni & 1) * 2],
                             bh[ni >> 1][(ni & 1) * 2 + 1]);

            uint32_t al[4][4];
#pragma unroll
            for (int mi = 0; mi < 4; ++mi) ldsm4(al[mi], a_addr + OFF_AL + mi * 16 * 80);
#pragma unroll
            for (int mi = 0; mi < 4; ++mi)
#pragma unroll
                for (int ni = 0; ni < 4; ++ni)
                    mma16816(acc[mi][ni], al[mi], bh[ni >> 1][(ni & 1) * 2],
                             bh[ni >> 1][(ni & 1) * 2 + 1]);

            uint32_t bl[2][4];
#pragma unroll
            for (int q = 0; q < 2; ++q)    ldsm4(bl[q], b_addr + OFF_BL + q * 16 * 80);
#pragma unroll
            for (int mi = 0; mi < 4; ++mi)
#pragma unroll
                for (int ni = 0; ni < 4; ++ni)
                    mma16816(acc[mi][ni], ah[mi], bl[ni >> 1][(ni & 1) * 2],
                             bl[ni >> 1][(ni & 1) * 2 + 1]);
        }

        if (c < 15) {
            CP_WAIT0();        // chunk c+1 data landed (overlapped with MMAs above)
            convert(c + 1);
        }
        __syncthreads();
    }

    // ---- epilogue: add db, store fp32 delta ----
#pragma unroll
    for (int ni = 0; ni < 4; ++ni) {
        int colL = wn * 32 + ni * 8 + ((lane & 3) << 1);
        int col  = ntile + colL;
        float db0 = db_s[colL];
        float db1 = db_s[colL + 1];
#pragma unroll
        for (int mi = 0; mi < 4; ++mi) {
            int row = wm * 64 + mi * 16 + (lane >> 2);
            float2 v0 = make_float2(acc[mi][ni][0] + db0, acc[mi][ni][1] + db1);
            float2 v1 = make_float2(acc[mi][ni][2] + db0, acc[mi][ni][3] + db1);
            *reinterpret_cast<float2*>(&g_S[(size_t)row * NPAD + col]) = v0;
            *reinterpret_cast<float2*>(&g_S[(size_t)(row + 8) * NPAD + col]) = v1;
        }
    }
}

// ---------------------------------------------------------------------------
// Tree kernel: 8 subtrees per batch row (depth-3 roots), grid (8, 256).
// ---------------------------------------------------------------------------
__device__ __forceinline__ void sig2(float delta, float& p0, float& p1) {
    float dc = fminf(fmaxf(delta, -30.f), 30.f);
    float t = __expf(-dc);
    float r = __fdividef(1.f, 1.f + t);
    p1 = r;
    p0 = t * r;
}

__global__ void __launch_bounds__(256) tree_kernel(float* __restrict__ out) {
    __shared__ float bufA[1024];
    __shared__ float bufB[1024];
    const int r   = blockIdx.x;   // subtree (depth-3 node index) 0..7
    const int b   = blockIdx.y;   // batch row
    const int tid = threadIdx.x;
    const float* S = g_S + (size_t)b * NPAD;

    // prefix through depths 0..2 along the path to depth-3 node r
    float P;
    {
        float p0, p1;
        sig2(S[0], p0, p1);                 P  = (r & 4) ? p1 : p0;
        sig2(S[1 + (r >> 2)], p0, p1);      P *= (r & 2) ? p1 : p0;
        sig2(S[3 + (r >> 1)], p0, p1);      P *= (r & 1) ? p1 : p0;
    }
    if (tid == 0) bufA[0] = P;
    __syncthreads();

    float* cur = bufA;
    float* nxt = bufB;
    int L = 1;
#pragma unroll
    for (int d = 3; d <= 12; ++d) {
        const int base = (1 << d) - 1 + r * L;
        for (int i = tid; i < L; i += 256) {
            float p0, p1;
            sig2(S[base + i], p0, p1);
            float cc = cur[i];
            nxt[2 * i]     = cc * p0;
            nxt[2 * i + 1] = cc * p1;
        }
        __syncthreads();
        float* t = cur; cur = nxt; nxt = t;
        L <<= 1;
    }

    // depth 13: L = 1024, write leaves straight to gmem
    float2* orow = reinterpret_cast<float2*>(out + (size_t)b * NPAD) + r * 1024;
    const int base = 8191 + r * 1024;
    for (int i = tid; i < 1024; i += 256) {
        float p0, p1;
        sig2(S[base + i], p0, p1);
        float cc = cur[i];
        orow[i] = make_float2(cc * p0, cc * p1);
    }
}

// ---------------------------------------------------------------------------
// Launch
// ---------------------------------------------------------------------------
extern "C" void kernel_launch(void* const* d_in, const int* in_sizes, int n_in,
                              void* d_out, int out_size) {
    const float* x    = (const float*)d_in[0];
    const float* W    = (const float*)d_in[1];
    const float* bvec = (const float*)d_in[2];
    // d_in[3]/d_in[4] (path_nodes/path_bits) encode a perfect heap; implicit.
    float* out = (float*)d_out;

    cudaFuncSetAttribute(gemm_f, cudaFuncAttributeMaxDynamicSharedMemorySize, GEMM_SMEM);

    prepA_kernel<<<128, 256>>>(x);
    gemm_f<<<128, 512, GEMM_SMEM>>>(W, bvec);
    tree_kernel<<<dim3(8, BATCH), 256>>>(out);
}